// round 2
// baseline (speedup 1.0000x reference)
#include <cuda_runtime.h>

#define N_NODES 50000
#define N_EDGES 1000000
#define HIDDEN  128
#define N_GAUSS 50
#define N_FILT  128
#define N_COLORS 4
#define CUTOFF_R 10.0f
#define LOG2F_  0.6931471805599453f
#define PI_F    3.14159265358979323846f

#define CH 1024              // edges per block-chunk (color-aligned)
#define NCHUNK 981           // covers E + max padding
#define PERM_SZ (NCHUNK*CH)  // 1,004,544
#define TE 64                // edge tile per inner iteration
#define SC_BS 4096

// ---- scratch (static device globals; no allocation allowed) ----
__device__ float g_h[N_NODES * HIDDEN];     // x @ lin1_w.T
__device__ float g_agg[N_NODES * N_FILT];   // segment-sum accumulator
__device__ int   g_perm[PERM_SZ];           // color-sorted edge ids, -1 = pad
__device__ int   g_cnt[N_COLORS];
__device__ int   g_cur[N_COLORS];

__device__ __forceinline__ float ssp(float v) {
    // shifted softplus: log(1+exp(v)) - log2, numerically stable, fast intrinsics
    return fmaxf(v, 0.0f) + __logf(1.0f + __expf(-fabsf(v))) - LOG2F_;
}

// ---------------------------------------------------------------- init
__global__ void init_kernel() {
    int idx = blockIdx.x * blockDim.x + threadIdx.x;
    int stride = gridDim.x * blockDim.x;
    for (int i = idx; i < N_NODES * N_FILT; i += stride) g_agg[i] = 0.0f;
    for (int i = idx; i < PERM_SZ; i += stride) g_perm[i] = -1;
    if (idx < N_COLORS) g_cnt[idx] = 0;
}

// ---------------------------------------------------------------- histogram
__global__ void hist_kernel(const int* __restrict__ colors) {
    __shared__ int sh[N_COLORS];
    if (threadIdx.x < N_COLORS) sh[threadIdx.x] = 0;
    __syncthreads();
    int idx = blockIdx.x * blockDim.x + threadIdx.x;
    int stride = gridDim.x * blockDim.x;
    for (int i = idx; i < N_EDGES; i += stride) atomicAdd(&sh[colors[i]], 1);
    __syncthreads();
    if (threadIdx.x < N_COLORS) atomicAdd(&g_cnt[threadIdx.x], sh[threadIdx.x]);
}

// ---------------------------------------------------------------- offsets (CH-aligned bases)
__global__ void offset_kernel() {
    if (blockIdx.x == 0 && threadIdx.x == 0) {
        int b = 0;
        for (int c = 0; c < N_COLORS; c++) {
            g_cur[c] = b;
            b += (g_cnt[c] + CH - 1) / CH * CH;
        }
    }
}

// ---------------------------------------------------------------- scatter (counting sort)
__global__ void scatter_kernel(const int* __restrict__ colors) {
    __shared__ int s_cnt[N_COLORS], s_base[N_COLORS];
    int t = threadIdx.x;
    if (t < N_COLORS) s_cnt[t] = 0;
    __syncthreads();
    int start = blockIdx.x * SC_BS;
    int end = min(start + SC_BS, N_EDGES);
    for (int i = start + t; i < end; i += blockDim.x) atomicAdd(&s_cnt[colors[i]], 1);
    __syncthreads();
    if (t < N_COLORS) { s_base[t] = atomicAdd(&g_cur[t], s_cnt[t]); s_cnt[t] = 0; }
    __syncthreads();
    for (int i = start + t; i < end; i += blockDim.x) {
        int c = colors[i];
        int pos = s_base[c] + atomicAdd(&s_cnt[c], 1);
        g_perm[pos] = i;
    }
}

// ---------------------------------------------------------------- lin1: g_h = x @ lin1_w.T
__global__ void __launch_bounds__(128) lin1_kernel(const float* __restrict__ x,
                                                   const float* __restrict__ w) {
    extern __shared__ float sm[];
    float* Wt = sm;                 // [k][f] 128*128
    float* xs = Wt + 128 * 128;     // 4*128
    int t = threadIdx.x;
    for (int i = t; i < 128 * 128; i += 128) {
        int f = i >> 7, k = i & 127;
        Wt[k * 128 + f] = w[i];
    }
    __syncthreads();
    int row0 = blockIdx.x * 128;
    for (int rg = 0; rg < 128; rg += 4) {
        int r = row0 + rg;
#pragma unroll
        for (int j = 0; j < 4; j++) {
            int rr = r + j;
            xs[j * 128 + t] = (rr < N_NODES) ? x[rr * 128 + t] : 0.0f;
        }
        __syncthreads();
        float a0 = 0, a1 = 0, a2 = 0, a3 = 0;
#pragma unroll 8
        for (int k = 0; k < 128; k++) {
            float wv = Wt[k * 128 + t];
            a0 += xs[k] * wv;
            a1 += xs[128 + k] * wv;
            a2 += xs[256 + k] * wv;
            a3 += xs[384 + k] * wv;
        }
        if (r + 0 < N_NODES) g_h[(r + 0) * 128 + t] = a0;
        if (r + 1 < N_NODES) g_h[(r + 1) * 128 + t] = a1;
        if (r + 2 < N_NODES) g_h[(r + 2) * 128 + t] = a2;
        if (r + 3 < N_NODES) g_h[(r + 3) * 128 + t] = a3;
        __syncthreads();
    }
}

// ---------------------------------------------------------------- fused edge kernel
// One block = one CH-chunk of color-sorted edges (uniform color).
// SMEM: W1t[g][f], W2t[k][f], biases, attr tile (transposed), hidden tile.
__global__ void __launch_bounds__(512, 1) edge_kernel(
    const int* __restrict__ edge_index,
    const float* __restrict__ ew,
    const float* __restrict__ attr,
    const int* __restrict__ colors,
    const float* __restrict__ m1w, const float* __restrict__ m1b,
    const float* __restrict__ m2w, const float* __restrict__ m2b)
{
    extern __shared__ float sm[];
    float* W1t    = sm;                  // 50*128   = 6400
    float* W2t    = W1t + 6400;          // 128*128  = 16384
    float* b1s    = W2t + 16384;         // 128
    float* b2s    = b1s + 128;           // 128
    float* attr_t = b2s + 128;           // 50*64    = 3200  ([g][e])
    float* hid_s  = attr_t + 3200;       // 64*128   = 8192  ([e][k])
    float* s_C    = hid_s + 8192;        // 64
    int*   s_src  = (int*)(s_C + 64);
    int*   s_dst  = s_src + 64;
    int*   s_p    = s_dst + 64;

    int t = threadIdx.x;
    int chunk0 = blockIdx.x * CH;
    int p0 = g_perm[chunk0];
    if (p0 < 0) return;                  // gap chunk (all pad)
    int c = colors[p0];

    // load this color's weights (once per block)
    const float* w1 = m1w + c * N_FILT * N_GAUSS;
    for (int i = t; i < N_FILT * N_GAUSS; i += 512) {
        int f = i / N_GAUSS, g = i - f * N_GAUSS;
        W1t[g * 128 + f] = w1[i];
    }
    const float* w2 = m2w + c * N_FILT * N_FILT;
    for (int i = t; i < N_FILT * N_FILT; i += 512) {
        int f = i >> 7, k = i & 127;
        W2t[k * 128 + f] = w2[i];
    }
    if (t < 128) { b1s[t] = m1b[c * 128 + t]; b2s[t] = m2b[c * 128 + t]; }
    __syncthreads();

    int fq = t & 31;    // feature quad: f = fq*4 .. fq*4+3
    int eq = t >> 5;    // edge quad (warp id): e = eq*4 .. eq*4+3

    for (int ts0 = chunk0; ts0 < chunk0 + CH; ts0 += TE) {
        // ---- edge metadata ----
        if (t < TE) {
            int p = g_perm[ts0 + t];
            s_p[t] = p;
            if (p >= 0) {
                s_src[t] = edge_index[p];
                s_dst[t] = edge_index[N_EDGES + p];
                s_C[t] = 0.5f * (__cosf(ew[p] * (PI_F / CUTOFF_R)) + 1.0f);
            } else {
                s_src[t] = 0; s_dst[t] = -1; s_C[t] = 0.0f;
            }
        }
        __syncthreads();
        // ---- attr tile, transposed [g][e] ----
        for (int i = t; i < TE * N_GAUSS; i += 512) {
            int e = i / N_GAUSS, g = i - e * N_GAUSS;
            int p = s_p[e];
            attr_t[g * TE + e] = (p >= 0) ? attr[p * N_GAUSS + g] : 0.0f;
        }
        __syncthreads();

        // ---- MLP1: hidden = ssp(attr @ W1^T + b1) ----
        float acc[4][4];
#pragma unroll
        for (int i = 0; i < 4; i++)
#pragma unroll
            for (int j = 0; j < 4; j++) acc[i][j] = 0.0f;

#pragma unroll 5
        for (int g = 0; g < N_GAUSS; g++) {
            float4 wv = *(const float4*)(W1t + g * 128 + fq * 4);
            float4 av = *(const float4*)(attr_t + g * TE + eq * 4);
            acc[0][0] += av.x * wv.x; acc[0][1] += av.x * wv.y; acc[0][2] += av.x * wv.z; acc[0][3] += av.x * wv.w;
            acc[1][0] += av.y * wv.x; acc[1][1] += av.y * wv.y; acc[1][2] += av.y * wv.z; acc[1][3] += av.y * wv.w;
            acc[2][0] += av.z * wv.x; acc[2][1] += av.z * wv.y; acc[2][2] += av.z * wv.z; acc[2][3] += av.z * wv.w;
            acc[3][0] += av.w * wv.x; acc[3][1] += av.w * wv.y; acc[3][2] += av.w * wv.z; acc[3][3] += av.w * wv.w;
        }
        float4 b1v = *(const float4*)(b1s + fq * 4);
#pragma unroll
        for (int ei = 0; ei < 4; ei++) {
            float4 hv;
            hv.x = ssp(acc[ei][0] + b1v.x);
            hv.y = ssp(acc[ei][1] + b1v.y);
            hv.z = ssp(acc[ei][2] + b1v.z);
            hv.w = ssp(acc[ei][3] + b1v.w);
            *(float4*)(hid_s + (eq * 4 + ei) * 128 + fq * 4) = hv;
        }
        __syncthreads();

        // ---- MLP2: W = hidden @ W2^T + b2, then * C, * h[src], scatter-add ----
        float a2[4][4];
#pragma unroll
        for (int i = 0; i < 4; i++)
#pragma unroll
            for (int j = 0; j < 4; j++) a2[i][j] = 0.0f;

#pragma unroll 4
        for (int kc = 0; kc < 32; kc++) {
            float4 w0 = *(const float4*)(W2t + (kc * 4 + 0) * 128 + fq * 4);
            float4 w1v = *(const float4*)(W2t + (kc * 4 + 1) * 128 + fq * 4);
            float4 w2v = *(const float4*)(W2t + (kc * 4 + 2) * 128 + fq * 4);
            float4 w3v = *(const float4*)(W2t + (kc * 4 + 3) * 128 + fq * 4);
#pragma unroll
            for (int ei = 0; ei < 4; ei++) {
                float4 h4 = *(const float4*)(hid_s + (eq * 4 + ei) * 128 + kc * 4);
                a2[ei][0] += h4.x * w0.x + h4.y * w1v.x + h4.z * w2v.x + h4.w * w3v.x;
                a2[ei][1] += h4.x * w0.y + h4.y * w1v.y + h4.z * w2v.y + h4.w * w3v.y;
                a2[ei][2] += h4.x * w0.z + h4.y * w1v.z + h4.z * w2v.z + h4.w * w3v.z;
                a2[ei][3] += h4.x * w0.w + h4.y * w1v.w + h4.z * w2v.w + h4.w * w3v.w;
            }
        }
        float4 b2v = *(const float4*)(b2s + fq * 4);
#pragma unroll
        for (int ei = 0; ei < 4; ei++) {
            int e = eq * 4 + ei;
            int dst = s_dst[e];
            if (dst >= 0) {
                float cc = s_C[e];
                int src = s_src[e];
                float4 hv = *(const float4*)(g_h + src * 128 + fq * 4);
                float m0 = (a2[ei][0] + b2v.x) * cc * hv.x;
                float m1 = (a2[ei][1] + b2v.y) * cc * hv.y;
                float m2 = (a2[ei][2] + b2v.z) * cc * hv.z;
                float m3 = (a2[ei][3] + b2v.w) * cc * hv.w;
                float* base = g_agg + dst * 128 + fq * 4;
                atomicAdd(base + 0, m0);
                atomicAdd(base + 1, m1);
                atomicAdd(base + 2, m2);
                atomicAdd(base + 3, m3);
            }
        }
        __syncthreads();
    }
}

// ---------------------------------------------------------------- output: ssp(agg@W2^T+b2)@W3^T+b3
__global__ void __launch_bounds__(128) out_kernel(
    const float* __restrict__ w2, const float* __restrict__ b2,
    const float* __restrict__ w3, const float* __restrict__ b3,
    float* __restrict__ out)
{
    extern __shared__ float sm[];
    float* W2t = sm;                // [k][f]
    float* W3t = W2t + 16384;
    float* as  = W3t + 16384;       // 4*128
    float* tss = as + 512;          // 4*128
    int t = threadIdx.x;
    for (int i = t; i < 16384; i += 128) {
        int f = i >> 7, k = i & 127;
        W2t[k * 128 + f] = w2[i];
        W3t[k * 128 + f] = w3[i];
    }
    float bb2 = b2[t], bb3 = b3[t];
    __syncthreads();
    int row0 = blockIdx.x * 128;
    for (int rg = 0; rg < 128; rg += 4) {
        int r = row0 + rg;
#pragma unroll
        for (int j = 0; j < 4; j++) {
            int rr = r + j;
            as[j * 128 + t] = (rr < N_NODES) ? g_agg[rr * 128 + t] : 0.0f;
        }
        __syncthreads();
        float a0 = 0, a1 = 0, a2 = 0, a3 = 0;
#pragma unroll 8
        for (int k = 0; k < 128; k++) {
            float wv = W2t[k * 128 + t];
            a0 += as[k] * wv;
            a1 += as[128 + k] * wv;
            a2 += as[256 + k] * wv;
            a3 += as[384 + k] * wv;
        }
        tss[0 * 128 + t] = ssp(a0 + bb2);
        tss[1 * 128 + t] = ssp(a1 + bb2);
        tss[2 * 128 + t] = ssp(a2 + bb2);
        tss[3 * 128 + t] = ssp(a3 + bb2);
        __syncthreads();
        float c0 = 0, c1 = 0, c2 = 0, c3 = 0;
#pragma unroll 8
        for (int k = 0; k < 128; k++) {
            float wv = W3t[k * 128 + t];
            c0 += tss[k] * wv;
            c1 += tss[128 + k] * wv;
            c2 += tss[256 + k] * wv;
            c3 += tss[384 + k] * wv;
        }
        if (r + 0 < N_NODES) out[(r + 0) * 128 + t] = c0 + bb3;
        if (r + 1 < N_NODES) out[(r + 1) * 128 + t] = c1 + bb3;
        if (r + 2 < N_NODES) out[(r + 2) * 128 + t] = c2 + bb3;
        if (r + 3 < N_NODES) out[(r + 3) * 128 + t] = c3 + bb3;
        __syncthreads();
    }
}

// ---------------------------------------------------------------- launch
#define EDGE_SMEM ((6400 + 16384 + 128 + 128 + 3200 + 8192 + 64) * 4 + 3 * 64 * 4)
#define LIN1_SMEM ((16384 + 512) * 4)
#define OUT_SMEM  ((16384 * 2 + 512 + 512) * 4)

extern "C" void kernel_launch(void* const* d_in, const int* in_sizes, int n_in,
                              void* d_out, int out_size) {
    const float* x    = (const float*)d_in[0];
    const int*   ei   = (const int*)d_in[1];
    const float* ew   = (const float*)d_in[2];
    const float* attr = (const float*)d_in[3];
    const int*   col  = (const int*)d_in[4];
    const float* m1w  = (const float*)d_in[5];
    const float* m1b  = (const float*)d_in[6];
    const float* m2w  = (const float*)d_in[7];
    const float* m2b  = (const float*)d_in[8];
    const float* l1w  = (const float*)d_in[9];
    const float* l2w  = (const float*)d_in[10];
    const float* l2b  = (const float*)d_in[11];
    const float* lw   = (const float*)d_in[12];
    const float* lb   = (const float*)d_in[13];
    float* out = (float*)d_out;

    cudaFuncSetAttribute(edge_kernel, cudaFuncAttributeMaxDynamicSharedMemorySize, EDGE_SMEM);
    cudaFuncSetAttribute(lin1_kernel, cudaFuncAttributeMaxDynamicSharedMemorySize, LIN1_SMEM);
    cudaFuncSetAttribute(out_kernel,  cudaFuncAttributeMaxDynamicSharedMemorySize, OUT_SMEM);

    init_kernel<<<2048, 256>>>();
    hist_kernel<<<512, 256>>>(col);
    offset_kernel<<<1, 1>>>();
    scatter_kernel<<<(N_EDGES + SC_BS - 1) / SC_BS, 256>>>(col);
    lin1_kernel<<<(N_NODES + 127) / 128, 128, LIN1_SMEM>>>(x, l1w);
    edge_kernel<<<NCHUNK, 512, EDGE_SMEM>>>(ei, ew, attr, col, m1w, m1b, m2w, m2b);
    out_kernel<<<(N_NODES + 127) / 128, 128, OUT_SMEM>>>(l2w, l2b, lw, lb, out);
}

// round 3
// speedup vs baseline: 1.0772x; 1.0772x over previous
#include <cuda_runtime.h>

#define N_NODES 50000
#define N_EDGES 1000000
#define HIDDEN  128
#define N_GAUSS 50
#define N_FILT  128
#define N_COLORS 4
#define CUTOFF_R 10.0f
#define LOG2F_  0.6931471805599453f
#define PI_F    3.14159265358979323846f

#define CH 1024              // edges per block-chunk (color-aligned)
#define NCHUNK 981           // covers E + max padding
#define PERM_SZ (NCHUNK*CH)  // 1,004,544
#define TE 64                // edge tile per inner iteration
#define SC_BS 4096

// ---- scratch (static device globals; no allocation allowed) ----
__device__ float g_h[N_NODES * HIDDEN];     // x @ lin1_w.T
__device__ float g_agg[N_NODES * N_FILT];   // segment-sum accumulator
__device__ int   g_perm[PERM_SZ];           // color-sorted edge ids, -1 = pad
__device__ int   g_cnt[N_COLORS];
__device__ int   g_cur[N_COLORS];

__device__ __forceinline__ float ssp(float v) {
    // shifted softplus: log(1+exp(v)) - log2, numerically stable, fast intrinsics
    return fmaxf(v, 0.0f) + __logf(1.0f + __expf(-fabsf(v))) - LOG2F_;
}

// ---- packed f32x2 helpers (FFMA2 path; ptxas won't emit these from C++) ----
typedef unsigned long long u64t;

__device__ __forceinline__ u64t pk2(float a, float b) {
    u64t r;
    asm("mov.b64 %0, {%1, %2};" : "=l"(r) : "f"(a), "f"(b));
    return r;
}
__device__ __forceinline__ u64t dup2(float a) {
    u64t r;
    asm("mov.b64 %0, {%1, %1};" : "=l"(r) : "f"(a));
    return r;
}
__device__ __forceinline__ void fma2(u64t& d, u64t a, u64t b) {
    asm("fma.rn.f32x2 %0, %1, %2, %0;" : "+l"(d) : "l"(a), "l"(b));
}
__device__ __forceinline__ void unpk2(u64t v, float& a, float& b) {
    asm("mov.b64 {%0, %1}, %2;" : "=f"(a), "=f"(b) : "l"(v));
}

// ---------------------------------------------------------------- init
__global__ void init_kernel() {
    int idx = blockIdx.x * blockDim.x + threadIdx.x;
    int stride = gridDim.x * blockDim.x;
    for (int i = idx; i < N_NODES * N_FILT; i += stride) g_agg[i] = 0.0f;
    for (int i = idx; i < PERM_SZ; i += stride) g_perm[i] = -1;
    if (idx < N_COLORS) g_cnt[idx] = 0;
}

// ---------------------------------------------------------------- histogram
__global__ void hist_kernel(const int* __restrict__ colors) {
    __shared__ int sh[N_COLORS];
    if (threadIdx.x < N_COLORS) sh[threadIdx.x] = 0;
    __syncthreads();
    int idx = blockIdx.x * blockDim.x + threadIdx.x;
    int stride = gridDim.x * blockDim.x;
    for (int i = idx; i < N_EDGES; i += stride) atomicAdd(&sh[colors[i]], 1);
    __syncthreads();
    if (threadIdx.x < N_COLORS) atomicAdd(&g_cnt[threadIdx.x], sh[threadIdx.x]);
}

// ---------------------------------------------------------------- offsets (CH-aligned bases)
__global__ void offset_kernel() {
    if (blockIdx.x == 0 && threadIdx.x == 0) {
        int b = 0;
        for (int c = 0; c < N_COLORS; c++) {
            g_cur[c] = b;
            b += (g_cnt[c] + CH - 1) / CH * CH;
        }
    }
}

// ---------------------------------------------------------------- scatter (counting sort)
__global__ void scatter_kernel(const int* __restrict__ colors) {
    __shared__ int s_cnt[N_COLORS], s_base[N_COLORS];
    int t = threadIdx.x;
    if (t < N_COLORS) s_cnt[t] = 0;
    __syncthreads();
    int start = blockIdx.x * SC_BS;
    int end = min(start + SC_BS, N_EDGES);
    for (int i = start + t; i < end; i += blockDim.x) atomicAdd(&s_cnt[colors[i]], 1);
    __syncthreads();
    if (t < N_COLORS) { s_base[t] = atomicAdd(&g_cur[t], s_cnt[t]); s_cnt[t] = 0; }
    __syncthreads();
    for (int i = start + t; i < end; i += blockDim.x) {
        int c = colors[i];
        int pos = s_base[c] + atomicAdd(&s_cnt[c], 1);
        g_perm[pos] = i;
    }
}

// ---------------------------------------------------------------- lin1: g_h = x @ lin1_w.T
__global__ void __launch_bounds__(128) lin1_kernel(const float* __restrict__ x,
                                                   const float* __restrict__ w) {
    extern __shared__ float sm[];
    float* Wt = sm;                 // [k][f] 128*128
    float* xs = Wt + 128 * 128;     // 4*128
    int t = threadIdx.x;
    for (int i = t; i < 128 * 128; i += 128) {
        int f = i >> 7, k = i & 127;
        Wt[k * 128 + f] = w[i];
    }
    __syncthreads();
    int row0 = blockIdx.x * 128;
    for (int rg = 0; rg < 128; rg += 4) {
        int r = row0 + rg;
#pragma unroll
        for (int j = 0; j < 4; j++) {
            int rr = r + j;
            xs[j * 128 + t] = (rr < N_NODES) ? x[rr * 128 + t] : 0.0f;
        }
        __syncthreads();
        float a0 = 0, a1 = 0, a2 = 0, a3 = 0;
#pragma unroll 8
        for (int k = 0; k < 128; k++) {
            float wv = Wt[k * 128 + t];
            a0 += xs[k] * wv;
            a1 += xs[128 + k] * wv;
            a2 += xs[256 + k] * wv;
            a3 += xs[384 + k] * wv;
        }
        if (r + 0 < N_NODES) g_h[(r + 0) * 128 + t] = a0;
        if (r + 1 < N_NODES) g_h[(r + 1) * 128 + t] = a1;
        if (r + 2 < N_NODES) g_h[(r + 2) * 128 + t] = a2;
        if (r + 3 < N_NODES) g_h[(r + 3) * 128 + t] = a3;
        __syncthreads();
    }
}

// ---------------------------------------------------------------- fused edge kernel
// One block = one CH-chunk of color-sorted edges (uniform color).
// Inner GEMMs use packed fma.rn.f32x2: 2 MAC per FMA-pipe issue slot.
__global__ void __launch_bounds__(512, 1) edge_kernel(
    const int* __restrict__ edge_index,
    const float* __restrict__ ew,
    const float* __restrict__ attr,
    const int* __restrict__ colors,
    const float* __restrict__ m1w, const float* __restrict__ m1b,
    const float* __restrict__ m2w, const float* __restrict__ m2b)
{
    extern __shared__ float sm[];
    float* W1t    = sm;                  // 50*128   = 6400
    float* W2t    = W1t + 6400;          // 128*128  = 16384
    float* b1s    = W2t + 16384;         // 128
    float* b2s    = b1s + 128;           // 128
    float* attr_t = b2s + 128;           // 50*64    = 3200  ([g][e])
    float* hid_s  = attr_t + 3200;       // 64*128   = 8192  ([e][k])
    float* s_C    = hid_s + 8192;        // 64
    int*   s_src  = (int*)(s_C + 64);
    int*   s_dst  = s_src + 64;
    int*   s_p    = s_dst + 64;

    int t = threadIdx.x;
    int chunk0 = blockIdx.x * CH;
    int p0 = g_perm[chunk0];
    if (p0 < 0) return;                  // gap chunk (all pad)
    int c = colors[p0];

    // load this color's weights (once per block)
    const float* w1 = m1w + c * N_FILT * N_GAUSS;
    for (int i = t; i < N_FILT * N_GAUSS; i += 512) {
        int f = i / N_GAUSS, g = i - f * N_GAUSS;
        W1t[g * 128 + f] = w1[i];
    }
    const float* w2 = m2w + c * N_FILT * N_FILT;
    for (int i = t; i < N_FILT * N_FILT; i += 512) {
        int f = i >> 7, k = i & 127;
        W2t[k * 128 + f] = w2[i];
    }
    if (t < 128) { b1s[t] = m1b[c * 128 + t]; b2s[t] = m2b[c * 128 + t]; }
    __syncthreads();

    int fq = t & 31;    // feature quad: f = fq*4 .. fq*4+3  (2 f32x2 pairs)
    int eq = t >> 5;    // edge quad (warp id): e = eq*4 .. eq*4+3

    for (int ts0 = chunk0; ts0 < chunk0 + CH; ts0 += TE) {
        // ---- edge metadata ----
        if (t < TE) {
            int p = g_perm[ts0 + t];
            s_p[t] = p;
            if (p >= 0) {
                s_src[t] = edge_index[p];
                s_dst[t] = edge_index[N_EDGES + p];
                s_C[t] = 0.5f * (__cosf(ew[p] * (PI_F / CUTOFF_R)) + 1.0f);
            } else {
                s_src[t] = 0; s_dst[t] = -1; s_C[t] = 0.0f;
            }
        }
        __syncthreads();
        // ---- attr tile, transposed [g][e] ----
        for (int i = t; i < TE * N_GAUSS; i += 512) {
            int e = i / N_GAUSS, g = i - e * N_GAUSS;
            int p = s_p[e];
            attr_t[g * TE + e] = (p >= 0) ? attr[p * N_GAUSS + g] : 0.0f;
        }
        __syncthreads();

        // ---- MLP1: hidden = ssp(attr @ W1^T + b1), f32x2 packed ----
        // acc1[edge][fpair]: each u64 = features (2f, 2f+1) for one edge
        u64t acc1[4][2];
#pragma unroll
        for (int i = 0; i < 4; i++) { acc1[i][0] = 0ull; acc1[i][1] = 0ull; }

#pragma unroll 5
        for (int g = 0; g < N_GAUSS; g++) {
            float4 w4 = *(const float4*)(W1t + g * 128 + fq * 4);
            u64t wp0 = pk2(w4.x, w4.y);
            u64t wp1 = pk2(w4.z, w4.w);
            float4 av = *(const float4*)(attr_t + g * TE + eq * 4); // broadcast in warp
            u64t a0 = dup2(av.x), a1 = dup2(av.y), a2 = dup2(av.z), a3 = dup2(av.w);
            fma2(acc1[0][0], a0, wp0); fma2(acc1[0][1], a0, wp1);
            fma2(acc1[1][0], a1, wp0); fma2(acc1[1][1], a1, wp1);
            fma2(acc1[2][0], a2, wp0); fma2(acc1[2][1], a2, wp1);
            fma2(acc1[3][0], a3, wp0); fma2(acc1[3][1], a3, wp1);
        }
        float4 b1v = *(const float4*)(b1s + fq * 4);
#pragma unroll
        for (int ei = 0; ei < 4; ei++) {
            float v0, v1, v2, v3;
            unpk2(acc1[ei][0], v0, v1);
            unpk2(acc1[ei][1], v2, v3);
            float4 hv;
            hv.x = ssp(v0 + b1v.x);
            hv.y = ssp(v1 + b1v.y);
            hv.z = ssp(v2 + b1v.z);
            hv.w = ssp(v3 + b1v.w);
            *(float4*)(hid_s + (eq * 4 + ei) * 128 + fq * 4) = hv;
        }
        __syncthreads();

        // ---- MLP2: W = hidden @ W2^T + b2, f32x2 packed ----
        u64t acc2[4][2];
#pragma unroll
        for (int i = 0; i < 4; i++) { acc2[i][0] = 0ull; acc2[i][1] = 0ull; }

#pragma unroll 4
        for (int kc = 0; kc < 32; kc++) {
            float4 w0 = *(const float4*)(W2t + (kc * 4 + 0) * 128 + fq * 4);
            float4 w1v = *(const float4*)(W2t + (kc * 4 + 1) * 128 + fq * 4);
            float4 w2v = *(const float4*)(W2t + (kc * 4 + 2) * 128 + fq * 4);
            float4 w3v = *(const float4*)(W2t + (kc * 4 + 3) * 128 + fq * 4);
            u64t w0p0 = pk2(w0.x, w0.y),  w0p1 = pk2(w0.z, w0.w);
            u64t w1p0 = pk2(w1v.x, w1v.y), w1p1 = pk2(w1v.z, w1v.w);
            u64t w2p0 = pk2(w2v.x, w2v.y), w2p1 = pk2(w2v.z, w2v.w);
            u64t w3p0 = pk2(w3v.x, w3v.y), w3p1 = pk2(w3v.z, w3v.w);
#pragma unroll
            for (int ei = 0; ei < 4; ei++) {
                float4 h4 = *(const float4*)(hid_s + (eq * 4 + ei) * 128 + kc * 4); // broadcast
                u64t h0 = dup2(h4.x), h1 = dup2(h4.y), h2 = dup2(h4.z), h3 = dup2(h4.w);
                fma2(acc2[ei][0], h0, w0p0); fma2(acc2[ei][1], h0, w0p1);
                fma2(acc2[ei][0], h1, w1p0); fma2(acc2[ei][1], h1, w1p1);
                fma2(acc2[ei][0], h2, w2p0); fma2(acc2[ei][1], h2, w2p1);
                fma2(acc2[ei][0], h3, w3p0); fma2(acc2[ei][1], h3, w3p1);
            }
        }
        float4 b2v = *(const float4*)(b2s + fq * 4);
#pragma unroll
        for (int ei = 0; ei < 4; ei++) {
            int e = eq * 4 + ei;
            int dst = s_dst[e];
            if (dst >= 0) {
                float cc = s_C[e];
                int src = s_src[e];
                float4 hv = *(const float4*)(g_h + src * 128 + fq * 4);
                float v0, v1, v2, v3;
                unpk2(acc2[ei][0], v0, v1);
                unpk2(acc2[ei][1], v2, v3);
                float m0 = (v0 + b2v.x) * cc * hv.x;
                float m1 = (v1 + b2v.y) * cc * hv.y;
                float m2 = (v2 + b2v.z) * cc * hv.z;
                float m3 = (v3 + b2v.w) * cc * hv.w;
                float* base = g_agg + dst * 128 + fq * 4;
                // vectorized no-return reduction: one L2 atomic op per 16B
                asm volatile("red.global.add.v4.f32 [%0], {%1, %2, %3, %4};"
                             :: "l"(base), "f"(m0), "f"(m1), "f"(m2), "f"(m3)
                             : "memory");
            }
        }
        __syncthreads();
    }
}

// ---------------------------------------------------------------- output: ssp(agg@W2^T+b2)@W3^T+b3
__global__ void __launch_bounds__(128) out_kernel(
    const float* __restrict__ w2, const float* __restrict__ b2,
    const float* __restrict__ w3, const float* __restrict__ b3,
    float* __restrict__ out)
{
    extern __shared__ float sm[];
    float* W2t = sm;                // [k][f]
    float* W3t = W2t + 16384;
    float* as  = W3t + 16384;       // 4*128
    float* tss = as + 512;          // 4*128
    int t = threadIdx.x;
    for (int i = t; i < 16384; i += 128) {
        int f = i >> 7, k = i & 127;
        W2t[k * 128 + f] = w2[i];
        W3t[k * 128 + f] = w3[i];
    }
    float bb2 = b2[t], bb3 = b3[t];
    __syncthreads();
    int row0 = blockIdx.x * 128;
    for (int rg = 0; rg < 128; rg += 4) {
        int r = row0 + rg;
#pragma unroll
        for (int j = 0; j < 4; j++) {
            int rr = r + j;
            as[j * 128 + t] = (rr < N_NODES) ? g_agg[rr * 128 + t] : 0.0f;
        }
        __syncthreads();
        float a0 = 0, a1 = 0, a2 = 0, a3 = 0;
#pragma unroll 8
        for (int k = 0; k < 128; k++) {
            float wv = W2t[k * 128 + t];
            a0 += as[k] * wv;
            a1 += as[128 + k] * wv;
            a2 += as[256 + k] * wv;
            a3 += as[384 + k] * wv;
        }
        tss[0 * 128 + t] = ssp(a0 + bb2);
        tss[1 * 128 + t] = ssp(a1 + bb2);
        tss[2 * 128 + t] = ssp(a2 + bb2);
        tss[3 * 128 + t] = ssp(a3 + bb2);
        __syncthreads();
        float c0 = 0, c1 = 0, c2 = 0, c3 = 0;
#pragma unroll 8
        for (int k = 0; k < 128; k++) {
            float wv = W3t[k * 128 + t];
            c0 += tss[k] * wv;
            c1 += tss[128 + k] * wv;
            c2 += tss[256 + k] * wv;
            c3 += tss[384 + k] * wv;
        }
        if (r + 0 < N_NODES) out[(r + 0) * 128 + t] = c0 + bb3;
        if (r + 1 < N_NODES) out[(r + 1) * 128 + t] = c1 + bb3;
        if (r + 2 < N_NODES) out[(r + 2) * 128 + t] = c2 + bb3;
        if (r + 3 < N_NODES) out[(r + 3) * 128 + t] = c3 + bb3;
        __syncthreads();
    }
}

// ---------------------------------------------------------------- launch
#define EDGE_SMEM ((6400 + 16384 + 128 + 128 + 3200 + 8192 + 64) * 4 + 3 * 64 * 4)
#define LIN1_SMEM ((16384 + 512) * 4)
#define OUT_SMEM  ((16384 * 2 + 512 + 512) * 4)

extern "C" void kernel_launch(void* const* d_in, const int* in_sizes, int n_in,
                              void* d_out, int out_size) {
    const float* x    = (const float*)d_in[0];
    const int*   ei   = (const int*)d_in[1];
    const float* ew   = (const float*)d_in[2];
    const float* attr = (const float*)d_in[3];
    const int*   col  = (const int*)d_in[4];
    const float* m1w  = (const float*)d_in[5];
    const float* m1b  = (const float*)d_in[6];
    const float* m2w  = (const float*)d_in[7];
    const float* m2b  = (const float*)d_in[8];
    const float* l1w  = (const float*)d_in[9];
    const float* l2w  = (const float*)d_in[10];
    const float* l2b  = (const float*)d_in[11];
    const float* lw   = (const float*)d_in[12];
    const float* lb   = (const float*)d_in[13];
    float* out = (float*)d_out;

    cudaFuncSetAttribute(edge_kernel, cudaFuncAttributeMaxDynamicSharedMemorySize, EDGE_SMEM);
    cudaFuncSetAttribute(lin1_kernel, cudaFuncAttributeMaxDynamicSharedMemorySize, LIN1_SMEM);
    cudaFuncSetAttribute(out_kernel,  cudaFuncAttributeMaxDynamicSharedMemorySize, OUT_SMEM);

    init_kernel<<<2048, 256>>>();
    hist_kernel<<<512, 256>>>(col);
    offset_kernel<<<1, 1>>>();
    scatter_kernel<<<(N_EDGES + SC_BS - 1) / SC_BS, 256>>>(col);
    lin1_kernel<<<(N_NODES + 127) / 128, 128, LIN1_SMEM>>>(x, l1w);
    edge_kernel<<<NCHUNK, 512, EDGE_SMEM>>>(ei, ew, attr, col, m1w, m1b, m2w, m2b);
    out_kernel<<<(N_NODES + 127) / 128, 128, OUT_SMEM>>>(l2w, l2b, lw, lb, out);
}

// round 5
// speedup vs baseline: 1.2296x; 1.1415x over previous
#include <cuda_runtime.h>

#define N_NODES 50000
#define N_EDGES 1000000
#define HIDDEN  128
#define N_GAUSS 50
#define N_FILT  128
#define N_COLORS 4
#define CUTOFF_R 10.0f
#define LOG2F_  0.6931471805599453f
#define PI_F    3.14159265358979323846f

#define CH 1024              // edges per block-chunk (color-aligned)
#define NCHUNK 981           // covers E + max padding
#define PERM_SZ (NCHUNK*CH)  // 1,004,544
#define SC_BS 4096
#define FULLM 0xffffffffu

// ---- scratch (static device globals; no allocation allowed) ----
__device__ float g_h[N_NODES * HIDDEN];     // x @ lin1_w.T
__device__ float g_agg[N_NODES * N_FILT];   // segment-sum accumulator
__device__ int   g_perm[PERM_SZ];           // color-sorted edge ids, -1 = pad
__device__ int   g_cnt[N_COLORS];
__device__ int   g_cur[N_COLORS];

__device__ __forceinline__ float ssp(float v) {
    return fmaxf(v, 0.0f) + __logf(1.0f + __expf(-fabsf(v))) - LOG2F_;
}

// ---- packed f32x2 helpers ----
typedef unsigned long long u64t;

__device__ __forceinline__ u64t dup2(float a) {
    u64t r;
    asm("mov.b64 %0, {%1, %1};" : "=l"(r) : "f"(a));
    return r;
}
__device__ __forceinline__ void fma2(u64t& d, u64t a, u64t b) {
    asm("fma.rn.f32x2 %0, %1, %2, %0;" : "+l"(d) : "l"(a), "l"(b));
}
__device__ __forceinline__ void unpk2(u64t v, float& a, float& b) {
    asm("mov.b64 {%0, %1}, %2;" : "=f"(a), "=f"(b) : "l"(v));
}

// ---------------------------------------------------------------- init
__global__ void init_kernel() {
    int idx = blockIdx.x * blockDim.x + threadIdx.x;
    int stride = gridDim.x * blockDim.x;
    for (int i = idx; i < N_NODES * N_FILT; i += stride) g_agg[i] = 0.0f;
    for (int i = idx; i < PERM_SZ; i += stride) g_perm[i] = -1;
    if (idx < N_COLORS) g_cnt[idx] = 0;
}

// ---------------------------------------------------------------- histogram
__global__ void hist_kernel(const int* __restrict__ colors) {
    __shared__ int sh[N_COLORS];
    if (threadIdx.x < N_COLORS) sh[threadIdx.x] = 0;
    __syncthreads();
    int idx = blockIdx.x * blockDim.x + threadIdx.x;
    int stride = gridDim.x * blockDim.x;
    for (int i = idx; i < N_EDGES; i += stride) atomicAdd(&sh[colors[i]], 1);
    __syncthreads();
    if (threadIdx.x < N_COLORS) atomicAdd(&g_cnt[threadIdx.x], sh[threadIdx.x]);
}

// ---------------------------------------------------------------- offsets (CH-aligned bases)
__global__ void offset_kernel() {
    if (blockIdx.x == 0 && threadIdx.x == 0) {
        int b = 0;
        for (int c = 0; c < N_COLORS; c++) {
            g_cur[c] = b;
            b += (g_cnt[c] + CH - 1) / CH * CH;
        }
    }
}

// ---------------------------------------------------------------- scatter (counting sort)
__global__ void scatter_kernel(const int* __restrict__ colors) {
    __shared__ int s_cnt[N_COLORS], s_base[N_COLORS];
    int t = threadIdx.x;
    if (t < N_COLORS) s_cnt[t] = 0;
    __syncthreads();
    int start = blockIdx.x * SC_BS;
    int end = min(start + SC_BS, N_EDGES);
    for (int i = start + t; i < end; i += blockDim.x) atomicAdd(&s_cnt[colors[i]], 1);
    __syncthreads();
    if (t < N_COLORS) { s_base[t] = atomicAdd(&g_cur[t], s_cnt[t]); s_cnt[t] = 0; }
    __syncthreads();
    for (int i = start + t; i < end; i += blockDim.x) {
        int c = colors[i];
        int pos = s_base[c] + atomicAdd(&s_cnt[c], 1);
        g_perm[pos] = i;
    }
}

// ---------------------------------------------------------------- lin1: g_h = x @ lin1_w.T
__global__ void __launch_bounds__(128) lin1_kernel(const float* __restrict__ x,
                                                   const float* __restrict__ w) {
    extern __shared__ float sm[];
    float* Wt = sm;                 // [k][f] 128*128
    float* xs = Wt + 128 * 128;     // 4*128
    int t = threadIdx.x;
    for (int i = t; i < 128 * 128; i += 128) {
        int f = i >> 7, k = i & 127;
        Wt[k * 128 + f] = w[i];
    }
    __syncthreads();
    int row0 = blockIdx.x * 128;
    for (int rg = 0; rg < 128; rg += 4) {
        int r = row0 + rg;
#pragma unroll
        for (int j = 0; j < 4; j++) {
            int rr = r + j;
            xs[j * 128 + t] = (rr < N_NODES) ? x[rr * 128 + t] : 0.0f;
        }
        __syncthreads();
        float a0 = 0, a1 = 0, a2 = 0, a3 = 0;
#pragma unroll 8
        for (int k = 0; k < 128; k++) {
            float wv = Wt[k * 128 + t];
            a0 += xs[k] * wv;
            a1 += xs[128 + k] * wv;
            a2 += xs[256 + k] * wv;
            a3 += xs[384 + k] * wv;
        }
        if (r + 0 < N_NODES) g_h[(r + 0) * 128 + t] = a0;
        if (r + 1 < N_NODES) g_h[(r + 1) * 128 + t] = a1;
        if (r + 2 < N_NODES) g_h[(r + 2) * 128 + t] = a2;
        if (r + 3 < N_NODES) g_h[(r + 3) * 128 + t] = a3;
        __syncthreads();
    }
}

// ---------------------------------------------------------------- fused edge kernel
// One block = one CH-chunk (uniform color). Each warp independently processes
// 64 edges (4 per iteration) with PRIVATE smem staging: no block barriers in
// the main loop. All f32x2 operands come out of SMEM ready-to-use:
//   - weights: ulonglong2 loads (LDS.128 -> two pairs)
//   - attr/hidden: stored pre-duplicated (v,v) -> broadcast loads, no dup movs
__global__ void __launch_bounds__(512, 1) edge_kernel(
    const int* __restrict__ edge_index,
    const float* __restrict__ ew,
    const float* __restrict__ attr,
    const int* __restrict__ colors,
    const float* __restrict__ m1w, const float* __restrict__ m1b,
    const float* __restrict__ m2w, const float* __restrict__ m2b)
{
    extern __shared__ float sm[];
    float* W1t    = sm;                       // 50*128  = 6400 floats
    float* W2t    = W1t + 6400;               // 128*128 = 16384 floats
    float* b1s    = W2t + 16384;              // 128
    float* b2s    = b1s + 128;                // 128
    u64t*  attr_d = (u64t*)(b2s + 128);       // 16 warps * 50g * 4e  (dup'd)
    u64t*  hid_d  = attr_d + 16 * 200;        // 16 warps * 4e * 128k (dup'd)

    int t = threadIdx.x;
    int chunk0 = blockIdx.x * CH;
    int p0c = g_perm[chunk0];
    if (p0c < 0) return;                      // gap chunk (all pad)
    int c = colors[p0c];

    // load this color's weights (once per block)
    const float* w1 = m1w + c * N_FILT * N_GAUSS;
    for (int i = t; i < N_FILT * N_GAUSS; i += 512) {
        int f = i / N_GAUSS, g = i - f * N_GAUSS;
        W1t[g * 128 + f] = w1[i];
    }
    const float* w2 = m2w + c * N_FILT * N_FILT;
    for (int i = t; i < N_FILT * N_FILT; i += 512) {
        int f = i >> 7, k = i & 127;
        W2t[k * 128 + f] = w2[i];
    }
    if (t < 128) { b1s[t] = m1b[c * 128 + t]; b2s[t] = m2b[c * 128 + t]; }
    __syncthreads();

    int wid = t >> 5;
    int fq  = t & 31;                          // this lane's feature quad
    u64t* attr_w = attr_d + wid * 200;         // [g][e] dup'd, 50*4
    u64t* hid_w  = hid_d + wid * 512;          // [e][k] dup'd, 4*128

    float4 b1v = *(const float4*)(b1s + fq * 4);
    float4 b2v = *(const float4*)(b2s + fq * 4);

    int ebase = chunk0 + wid * 64;

    for (int it = 0; it < 16; it++) {
        int e0 = ebase + it * 4;
        // ---- per-edge metadata in lanes 0..3 ----
        int p = -1, src = 0, dst = -1;
        float C = 0.0f;
        if (fq < 4) {
            p = g_perm[e0 + fq];
            if (p >= 0) {
                src = edge_index[p];
                dst = edge_index[N_EDGES + p];
                C = 0.5f * (__cosf(ew[p] * (PI_F / CUTOFF_R)) + 1.0f);
            }
        }
        // broadcast the 4 edge ids to ALL lanes while the warp is converged
        // (shfl inside the divergent staging loop below was the R3 crash)
        int pe0 = __shfl_sync(FULLM, p, 0);
        int pe1 = __shfl_sync(FULLM, p, 1);
        int pe2 = __shfl_sync(FULLM, p, 2);
        int pe3 = __shfl_sync(FULLM, p, 3);

        // ---- stage attr (duplicated) into private region ----
#pragma unroll
        for (int idx = fq; idx < 200; idx += 32) {
            int e = idx / 50, g = idx - e * 50;
            int pe = (e == 0) ? pe0 : (e == 1) ? pe1 : (e == 2) ? pe2 : pe3;
            float v = (pe >= 0) ? __ldg(attr + pe * N_GAUSS + g) : 0.0f;
            attr_w[g * 4 + e] = dup2(v);
        }
        __syncwarp();

        // ---- MLP1: hidden = ssp(attr @ W1^T + b1) ----
        u64t acc1[4][2];
#pragma unroll
        for (int i = 0; i < 4; i++) { acc1[i][0] = 0ull; acc1[i][1] = 0ull; }
#pragma unroll 10
        for (int g = 0; g < N_GAUSS; g++) {
            ulonglong2 wp = *(const ulonglong2*)(W1t + g * 128 + fq * 4);
            ulonglong2 a01 = *(const ulonglong2*)(attr_w + g * 4);
            ulonglong2 a23 = *(const ulonglong2*)(attr_w + g * 4 + 2);
            fma2(acc1[0][0], a01.x, wp.x); fma2(acc1[0][1], a01.x, wp.y);
            fma2(acc1[1][0], a01.y, wp.x); fma2(acc1[1][1], a01.y, wp.y);
            fma2(acc1[2][0], a23.x, wp.x); fma2(acc1[2][1], a23.x, wp.y);
            fma2(acc1[3][0], a23.y, wp.x); fma2(acc1[3][1], a23.y, wp.y);
        }
        // bias + ssp, write hidden DUPLICATED: hid_w[e*128 + k] = (h,h)
#pragma unroll
        for (int ei = 0; ei < 4; ei++) {
            float v0, v1, v2, v3;
            unpk2(acc1[ei][0], v0, v1);
            unpk2(acc1[ei][1], v2, v3);
            float h0 = ssp(v0 + b1v.x);
            float h1 = ssp(v1 + b1v.y);
            float h2 = ssp(v2 + b1v.z);
            float h3 = ssp(v3 + b1v.w);
            float4* dst4 = (float4*)(hid_w + ei * 128 + fq * 4);
            dst4[0] = make_float4(h0, h0, h1, h1);
            dst4[1] = make_float4(h2, h2, h3, h3);
        }
        __syncwarp();

        // ---- MLP2: W = hidden @ W2^T + b2 ----
        u64t acc2[4][2];
#pragma unroll
        for (int i = 0; i < 4; i++) { acc2[i][0] = 0ull; acc2[i][1] = 0ull; }
#pragma unroll 4
        for (int kc = 0; kc < 32; kc++) {
            ulonglong2 wk0 = *(const ulonglong2*)(W2t + (kc * 4 + 0) * 128 + fq * 4);
            ulonglong2 wk1 = *(const ulonglong2*)(W2t + (kc * 4 + 1) * 128 + fq * 4);
            ulonglong2 wk2 = *(const ulonglong2*)(W2t + (kc * 4 + 2) * 128 + fq * 4);
            ulonglong2 wk3 = *(const ulonglong2*)(W2t + (kc * 4 + 3) * 128 + fq * 4);
#pragma unroll
            for (int ei = 0; ei < 4; ei++) {
                ulonglong2 h01 = *(const ulonglong2*)(hid_w + ei * 128 + kc * 4);     // (k,k+1) dup'd
                ulonglong2 h23 = *(const ulonglong2*)(hid_w + ei * 128 + kc * 4 + 2); // (k+2,k+3)
                fma2(acc2[ei][0], h01.x, wk0.x); fma2(acc2[ei][1], h01.x, wk0.y);
                fma2(acc2[ei][0], h01.y, wk1.x); fma2(acc2[ei][1], h01.y, wk1.y);
                fma2(acc2[ei][0], h23.x, wk2.x); fma2(acc2[ei][1], h23.x, wk2.y);
                fma2(acc2[ei][0], h23.y, wk3.x); fma2(acc2[ei][1], h23.y, wk3.y);
            }
        }
        // ---- epilogue: *C, *h[src], scatter-add ----
#pragma unroll
        for (int ei = 0; ei < 4; ei++) {
            int dste = __shfl_sync(FULLM, dst, ei);   // warp-converged here
            int srce = __shfl_sync(FULLM, src, ei);
            float Ce = __shfl_sync(FULLM, C, ei);
            if (dste >= 0) {                           // warp-uniform branch
                float4 hv = *(const float4*)(g_h + srce * 128 + fq * 4);
                float v0, v1, v2, v3;
                unpk2(acc2[ei][0], v0, v1);
                unpk2(acc2[ei][1], v2, v3);
                float m0 = (v0 + b2v.x) * Ce * hv.x;
                float m1 = (v1 + b2v.y) * Ce * hv.y;
                float m2 = (v2 + b2v.z) * Ce * hv.z;
                float m3 = (v3 + b2v.w) * Ce * hv.w;
                float* base = g_agg + dste * 128 + fq * 4;
                asm volatile("red.global.add.v4.f32 [%0], {%1, %2, %3, %4};"
                             :: "l"(base), "f"(m0), "f"(m1), "f"(m2), "f"(m3)
                             : "memory");
            }
        }
        __syncwarp();   // protect hid_w / attr_w reuse next iteration
    }
}

// ---------------------------------------------------------------- output: ssp(agg@W2^T+b2)@W3^T+b3
__global__ void __launch_bounds__(128) out_kernel(
    const float* __restrict__ w2, const float* __restrict__ b2,
    const float* __restrict__ w3, const float* __restrict__ b3,
    float* __restrict__ out)
{
    extern __shared__ float sm[];
    float* W2t = sm;                // [k][f]
    float* W3t = W2t + 16384;
    float* as  = W3t + 16384;       // 4*128
    float* tss = as + 512;          // 4*128
    int t = threadIdx.x;
    for (int i = t; i < 16384; i += 128) {
        int f = i >> 7, k = i & 127;
        W2t[k * 128 + f] = w2[i];
        W3t[k * 128 + f] = w3[i];
    }
    float bb2 = b2[t], bb3 = b3[t];
    __syncthreads();
    int row0 = blockIdx.x * 128;
    for (int rg = 0; rg < 128; rg += 4) {
        int r = row0 + rg;
#pragma unroll
        for (int j = 0; j < 4; j++) {
            int rr = r + j;
            as[j * 128 + t] = (rr < N_NODES) ? g_agg[rr * 128 + t] : 0.0f;
        }
        __syncthreads();
        float a0 = 0, a1 = 0, a2 = 0, a3 = 0;
#pragma unroll 8
        for (int k = 0; k < 128; k++) {
            float wv = W2t[k * 128 + t];
            a0 += as[k] * wv;
            a1 += as[128 + k] * wv;
            a2 += as[256 + k] * wv;
            a3 += as[384 + k] * wv;
        }
        tss[0 * 128 + t] = ssp(a0 + bb2);
        tss[1 * 128 + t] = ssp(a1 + bb2);
        tss[2 * 128 + t] = ssp(a2 + bb2);
        tss[3 * 128 + t] = ssp(a3 + bb2);
        __syncthreads();
        float c0 = 0, c1 = 0, c2 = 0, c3 = 0;
#pragma unroll 8
        for (int k = 0; k < 128; k++) {
            float wv = W3t[k * 128 + t];
            c0 += tss[k] * wv;
            c1 += tss[128 + k] * wv;
            c2 += tss[256 + k] * wv;
            c3 += tss[384 + k] * wv;
        }
        if (r + 0 < N_NODES) out[(r + 0) * 128 + t] = c0 + bb3;
        if (r + 1 < N_NODES) out[(r + 1) * 128 + t] = c1 + bb3;
        if (r + 2 < N_NODES) out[(r + 2) * 128 + t] = c2 + bb3;
        if (r + 3 < N_NODES) out[(r + 3) * 128 + t] = c3 + bb3;
        __syncthreads();
    }
}

// ---------------------------------------------------------------- launch
// floats: 6400+16384+256 = 23040 -> 92160 B ; u64 dup regions: 16*200 + 16*512 = 11392 -> 91136 B
#define EDGE_SMEM (23040 * 4 + 11392 * 8)
#define LIN1_SMEM ((16384 + 512) * 4)
#define OUT_SMEM  ((16384 * 2 + 512 + 512) * 4)

extern "C" void kernel_launch(void* const* d_in, const int* in_sizes, int n_in,
                              void* d_out, int out_size) {
    const float* x    = (const float*)d_in[0];
    const int*   ei   = (const int*)d_in[1];
    const float* ew   = (const float*)d_in[2];
    const float* attr = (const float*)d_in[3];
    const int*   col  = (const int*)d_in[4];
    const float* m1w  = (const float*)d_in[5];
    const float* m1b  = (const float*)d_in[6];
    const float* m2w  = (const float*)d_in[7];
    const float* m2b  = (const float*)d_in[8];
    const float* l1w  = (const float*)d_in[9];
    const float* l2w  = (const float*)d_in[10];
    const float* l2b  = (const float*)d_in[11];
    const float* lw   = (const float*)d_in[12];
    const float* lb   = (const float*)d_in[13];
    float* out = (float*)d_out;

    cudaFuncSetAttribute(edge_kernel, cudaFuncAttributeMaxDynamicSharedMemorySize, EDGE_SMEM);
    cudaFuncSetAttribute(lin1_kernel, cudaFuncAttributeMaxDynamicSharedMemorySize, LIN1_SMEM);
    cudaFuncSetAttribute(out_kernel,  cudaFuncAttributeMaxDynamicSharedMemorySize, OUT_SMEM);

    init_kernel<<<2048, 256>>>();
    hist_kernel<<<512, 256>>>(col);
    offset_kernel<<<1, 1>>>();
    scatter_kernel<<<(N_EDGES + SC_BS - 1) / SC_BS, 256>>>(col);
    lin1_kernel<<<(N_NODES + 127) / 128, 128, LIN1_SMEM>>>(x, l1w);
    edge_kernel<<<NCHUNK, 512, EDGE_SMEM>>>(ei, ew, attr, col, m1w, m1b, m2w, m2b);
    out_kernel<<<(N_NODES + 127) / 128, 128, OUT_SMEM>>>(l2w, l2b, lw, lb, out);
}

// round 7
// speedup vs baseline: 1.3228x; 1.0758x over previous
#include <cuda_runtime.h>

#define N_NODES 50000
#define N_EDGES 1000000
#define HIDDEN  128
#define N_GAUSS 50
#define N_FILT  128
#define N_COLORS 4
#define CUTOFF_R 10.0f
#define LOG2F_  0.6931471805599453f
#define PI_F    3.14159265358979323846f

#define CH 1024              // edges per block-chunk (color-aligned)
#define NCHUNK 981           // covers E + max padding
#define PERM_SZ (NCHUNK*CH)  // 1,004,544
#define SC_BS 4096
#define FULLM 0xffffffffu

// ---- scratch (static device globals; no allocation allowed) ----
__device__ float g_h[N_NODES * HIDDEN];     // x @ lin1_w.T
__device__ float g_agg[N_NODES * N_FILT];   // segment-sum accumulator
__device__ int   g_perm[PERM_SZ];           // color-sorted edge ids, -1 = pad
__device__ int   g_cnt[N_COLORS];
__device__ int   g_cur[N_COLORS];

__device__ __forceinline__ float ssp(float v) {
    return fmaxf(v, 0.0f) + __logf(1.0f + __expf(-fabsf(v))) - LOG2F_;
}

// ---- packed f32x2 helpers ----
typedef unsigned long long u64t;

__device__ __forceinline__ u64t dup2(float a) {
    u64t r;
    asm("mov.b64 %0, {%1, %1};" : "=l"(r) : "f"(a));
    return r;
}
__device__ __forceinline__ void fma2(u64t& d, u64t a, u64t b) {
    asm("fma.rn.f32x2 %0, %1, %2, %0;" : "+l"(d) : "l"(a), "l"(b));
}
__device__ __forceinline__ void unpk2(u64t v, float& a, float& b) {
    asm("mov.b64 {%0, %1}, %2;" : "=f"(a), "=f"(b) : "l"(v));
}

// ---------------------------------------------------------------- init
__global__ void init_kernel() {
    int idx = blockIdx.x * blockDim.x + threadIdx.x;
    int stride = gridDim.x * blockDim.x;
    for (int i = idx; i < N_NODES * N_FILT; i += stride) g_agg[i] = 0.0f;
    for (int i = idx; i < PERM_SZ; i += stride) g_perm[i] = -1;
    if (idx < N_COLORS) g_cnt[idx] = 0;
}

// ---------------------------------------------------------------- histogram
__global__ void hist_kernel(const int* __restrict__ colors) {
    __shared__ int sh[N_COLORS];
    if (threadIdx.x < N_COLORS) sh[threadIdx.x] = 0;
    __syncthreads();
    int idx = blockIdx.x * blockDim.x + threadIdx.x;
    int stride = gridDim.x * blockDim.x;
    for (int i = idx; i < N_EDGES; i += stride) atomicAdd(&sh[colors[i]], 1);
    __syncthreads();
    if (threadIdx.x < N_COLORS) atomicAdd(&g_cnt[threadIdx.x], sh[threadIdx.x]);
}

// ---------------------------------------------------------------- offsets (CH-aligned bases)
__global__ void offset_kernel() {
    if (blockIdx.x == 0 && threadIdx.x == 0) {
        int b = 0;
        for (int c = 0; c < N_COLORS; c++) {
            g_cur[c] = b;
            b += (g_cnt[c] + CH - 1) / CH * CH;
        }
    }
}

// ---------------------------------------------------------------- scatter (counting sort)
__global__ void scatter_kernel(const int* __restrict__ colors) {
    __shared__ int s_cnt[N_COLORS], s_base[N_COLORS];
    int t = threadIdx.x;
    if (t < N_COLORS) s_cnt[t] = 0;
    __syncthreads();
    int start = blockIdx.x * SC_BS;
    int end = min(start + SC_BS, N_EDGES);
    for (int i = start + t; i < end; i += blockDim.x) atomicAdd(&s_cnt[colors[i]], 1);
    __syncthreads();
    if (t < N_COLORS) { s_base[t] = atomicAdd(&g_cur[t], s_cnt[t]); s_cnt[t] = 0; }
    __syncthreads();
    for (int i = start + t; i < end; i += blockDim.x) {
        int c = colors[i];
        int pos = s_base[c] + atomicAdd(&s_cnt[c], 1);
        g_perm[pos] = i;
    }
}

// ---------------------------------------------------------------- lin1: g_h = x @ lin1_w.T
__global__ void __launch_bounds__(128) lin1_kernel(const float* __restrict__ x,
                                                   const float* __restrict__ w) {
    extern __shared__ float sm[];
    float* Wt = sm;                 // [k][f] 128*128
    float* xs = Wt + 128 * 128;     // 4*128
    int t = threadIdx.x;
    for (int i = t; i < 128 * 128; i += 128) {
        int f = i >> 7, k = i & 127;
        Wt[k * 128 + f] = w[i];
    }
    __syncthreads();
    int row0 = blockIdx.x * 128;
    for (int rg = 0; rg < 128; rg += 4) {
        int r = row0 + rg;
#pragma unroll
        for (int j = 0; j < 4; j++) {
            int rr = r + j;
            xs[j * 128 + t] = (rr < N_NODES) ? x[rr * 128 + t] : 0.0f;
        }
        __syncthreads();
        float a0 = 0, a1 = 0, a2 = 0, a3 = 0;
#pragma unroll 8
        for (int k = 0; k < 128; k++) {
            float wv = Wt[k * 128 + t];
            a0 += xs[k] * wv;
            a1 += xs[128 + k] * wv;
            a2 += xs[256 + k] * wv;
            a3 += xs[384 + k] * wv;
        }
        if (r + 0 < N_NODES) g_h[(r + 0) * 128 + t] = a0;
        if (r + 1 < N_NODES) g_h[(r + 1) * 128 + t] = a1;
        if (r + 2 < N_NODES) g_h[(r + 2) * 128 + t] = a2;
        if (r + 3 < N_NODES) g_h[(r + 3) * 128 + t] = a3;
        __syncthreads();
    }
}

// ---------------------------------------------------------------- fused edge kernel
// One block = one CH-chunk (uniform color). Each warp independently processes
// 64 edges, 8 PER ITERATION (amortizes the lane-distinct weight LDS, the
// crossbar-binding resource). attr/hidden staged as plain floats (broadcast
// loads are crossbar-free); (v,v) operand pairs rebuilt with ALU dup movs.
__global__ void __launch_bounds__(512, 1) edge_kernel(
    const int* __restrict__ edge_index,
    const float* __restrict__ ew,
    const float* __restrict__ attr,
    const int* __restrict__ colors,
    const float* __restrict__ m1w, const float* __restrict__ m1b,
    const float* __restrict__ m2w, const float* __restrict__ m2b)
{
    extern __shared__ float sm[];
    float* W1t    = sm;                       // 50*128  = 6400 floats
    float* W2t    = W1t + 6400;               // 128*128 = 16384 floats
    float* b1s    = W2t + 16384;              // 128
    float* b2s    = b1s + 128;                // 128
    float* attr_f = b2s + 128;                // 16 warps * 50g * 8e  = 6400
    float* hid_f  = attr_f + 16 * 400;        // 16 warps * 8e * 128k = 16384

    int t = threadIdx.x;
    int chunk0 = blockIdx.x * CH;
    int p0c = g_perm[chunk0];
    if (p0c < 0) return;                      // gap chunk (all pad)
    int c = colors[p0c];

    // load this color's weights (once per block)
    const float* w1 = m1w + c * N_FILT * N_GAUSS;
    for (int i = t; i < N_FILT * N_GAUSS; i += 512) {
        int f = i / N_GAUSS, g = i - f * N_GAUSS;
        W1t[g * 128 + f] = w1[i];
    }
    const float* w2 = m2w + c * N_FILT * N_FILT;
    for (int i = t; i < N_FILT * N_FILT; i += 512) {
        int f = i >> 7, k = i & 127;
        W2t[k * 128 + f] = w2[i];
    }
    if (t < 128) { b1s[t] = m1b[c * 128 + t]; b2s[t] = m2b[c * 128 + t]; }
    __syncthreads();

    int wid = t >> 5;
    int fq  = t & 31;                          // this lane's feature quad
    float* attr_w = attr_f + wid * 400;        // [g][e] plain, 50*8
    float* hid_w  = hid_f + wid * 1024;        // [e][k] plain, 8*128

    float4 b1v = *(const float4*)(b1s + fq * 4);
    float4 b2v = *(const float4*)(b2s + fq * 4);

    int ebase = chunk0 + wid * 64;

    for (int it = 0; it < 8; it++) {
        int e0 = ebase + it * 8;
        // ---- per-edge metadata in lanes 0..7 ----
        int p = -1, src = 0, dst = -1;
        float C = 0.0f;
        if (fq < 8) {
            p = g_perm[e0 + fq];
            if (p >= 0) {
                src = edge_index[p];
                dst = edge_index[N_EDGES + p];
                C = 0.5f * (__cosf(ew[p] * (PI_F / CUTOFF_R)) + 1.0f);
            }
        }
        // broadcast the 8 edge ids while the warp is converged
        int pe0 = __shfl_sync(FULLM, p, 0);
        int pe1 = __shfl_sync(FULLM, p, 1);
        int pe2 = __shfl_sync(FULLM, p, 2);
        int pe3 = __shfl_sync(FULLM, p, 3);
        int pe4 = __shfl_sync(FULLM, p, 4);
        int pe5 = __shfl_sync(FULLM, p, 5);
        int pe6 = __shfl_sync(FULLM, p, 6);
        int pe7 = __shfl_sync(FULLM, p, 7);

        // ---- stage attr [g][e] (plain floats); no sync ops in divergent path ----
#pragma unroll
        for (int i = 0; i < 13; i++) {
            int idx = i * 32 + fq;             // layout idx = g*8 + e
            if (idx < 400) {
                int e = idx & 7, g = idx >> 3;
                int pe = (e == 0) ? pe0 : (e == 1) ? pe1 : (e == 2) ? pe2 : (e == 3) ? pe3
                       : (e == 4) ? pe4 : (e == 5) ? pe5 : (e == 6) ? pe6 : pe7;
                float v = (pe >= 0) ? __ldg(attr + pe * N_GAUSS + g) : 0.0f;
                attr_w[idx] = v;
            }
        }
        __syncwarp();

        // ---- MLP1: hidden = ssp(attr @ W1^T + b1) ----
        u64t acc1[8][2];
#pragma unroll
        for (int i = 0; i < 8; i++) { acc1[i][0] = 0ull; acc1[i][1] = 0ull; }
#pragma unroll 5
        for (int g = 0; g < N_GAUSS; g++) {
            ulonglong2 wp = *(const ulonglong2*)(W1t + g * 128 + fq * 4);   // lane-distinct
            float4 a03 = *(const float4*)(attr_w + g * 8);                  // broadcast
            float4 a47 = *(const float4*)(attr_w + g * 8 + 4);              // broadcast
            u64t d0 = dup2(a03.x), d1 = dup2(a03.y), d2 = dup2(a03.z), d3 = dup2(a03.w);
            u64t d4 = dup2(a47.x), d5 = dup2(a47.y), d6 = dup2(a47.z), d7 = dup2(a47.w);
            fma2(acc1[0][0], d0, wp.x); fma2(acc1[0][1], d0, wp.y);
            fma2(acc1[1][0], d1, wp.x); fma2(acc1[1][1], d1, wp.y);
            fma2(acc1[2][0], d2, wp.x); fma2(acc1[2][1], d2, wp.y);
            fma2(acc1[3][0], d3, wp.x); fma2(acc1[3][1], d3, wp.y);
            fma2(acc1[4][0], d4, wp.x); fma2(acc1[4][1], d4, wp.y);
            fma2(acc1[5][0], d5, wp.x); fma2(acc1[5][1], d5, wp.y);
            fma2(acc1[6][0], d6, wp.x); fma2(acc1[6][1], d6, wp.y);
            fma2(acc1[7][0], d7, wp.x); fma2(acc1[7][1], d7, wp.y);
        }
        // bias + ssp, store hidden plain: hid_w[e*128 + fq*4..]
#pragma unroll
        for (int ei = 0; ei < 8; ei++) {
            float v0, v1, v2, v3;
            unpk2(acc1[ei][0], v0, v1);
            unpk2(acc1[ei][1], v2, v3);
            float4 hv;
            hv.x = ssp(v0 + b1v.x);
            hv.y = ssp(v1 + b1v.y);
            hv.z = ssp(v2 + b1v.z);
            hv.w = ssp(v3 + b1v.w);
            *(float4*)(hid_w + ei * 128 + fq * 4) = hv;
        }
        __syncwarp();

        // ---- MLP2: W = hidden @ W2^T + b2 ----
        u64t acc2[8][2];
#pragma unroll
        for (int i = 0; i < 8; i++) { acc2[i][0] = 0ull; acc2[i][1] = 0ull; }
#pragma unroll 2
        for (int kc = 0; kc < 32; kc++) {
            ulonglong2 wk0 = *(const ulonglong2*)(W2t + (kc * 4 + 0) * 128 + fq * 4);
            ulonglong2 wk1 = *(const ulonglong2*)(W2t + (kc * 4 + 1) * 128 + fq * 4);
            ulonglong2 wk2 = *(const ulonglong2*)(W2t + (kc * 4 + 2) * 128 + fq * 4);
            ulonglong2 wk3 = *(const ulonglong2*)(W2t + (kc * 4 + 3) * 128 + fq * 4);
#pragma unroll
            for (int ei = 0; ei < 8; ei++) {
                float4 h4 = *(const float4*)(hid_w + ei * 128 + kc * 4);    // broadcast
                u64t d0 = dup2(h4.x), d1 = dup2(h4.y), d2 = dup2(h4.z), d3 = dup2(h4.w);
                fma2(acc2[ei][0], d0, wk0.x); fma2(acc2[ei][1], d0, wk0.y);
                fma2(acc2[ei][0], d1, wk1.x); fma2(acc2[ei][1], d1, wk1.y);
                fma2(acc2[ei][0], d2, wk2.x); fma2(acc2[ei][1], d2, wk2.y);
                fma2(acc2[ei][0], d3, wk3.x); fma2(acc2[ei][1], d3, wk3.y);
            }
        }
        // ---- epilogue: *C, *h[src], scatter-add ----
#pragma unroll
        for (int ei = 0; ei < 8; ei++) {
            int dste = __shfl_sync(FULLM, dst, ei);   // warp-converged
            int srce = __shfl_sync(FULLM, src, ei);
            float Ce = __shfl_sync(FULLM, C, ei);
            if (dste >= 0) {                           // warp-uniform branch
                float4 hv = *(const float4*)(g_h + srce * 128 + fq * 4);
                float v0, v1, v2, v3;
                unpk2(acc2[ei][0], v0, v1);
                unpk2(acc2[ei][1], v2, v3);
                float m0 = (v0 + b2v.x) * Ce * hv.x;
                float m1 = (v1 + b2v.y) * Ce * hv.y;
                float m2 = (v2 + b2v.z) * Ce * hv.z;
                float m3 = (v3 + b2v.w) * Ce * hv.w;
                float* base = g_agg + dste * 128 + fq * 4;
                asm volatile("red.global.add.v4.f32 [%0], {%1, %2, %3, %4};"
                             :: "l"(base), "f"(m0), "f"(m1), "f"(m2), "f"(m3)
                             : "memory");
            }
        }
        __syncwarp();   // protect hid_w / attr_w reuse next iteration
    }
}

// ---------------------------------------------------------------- output: ssp(agg@W2^T+b2)@W3^T+b3
__global__ void __launch_bounds__(128) out_kernel(
    const float* __restrict__ w2, const float* __restrict__ b2,
    const float* __restrict__ w3, const float* __restrict__ b3,
    float* __restrict__ out)
{
    extern __shared__ float sm[];
    float* W2t = sm;                // [k][f]
    float* W3t = W2t + 16384;
    float* as  = W3t + 16384;       // 4*128
    float* tss = as + 512;          // 4*128
    int t = threadIdx.x;
    for (int i = t; i < 16384; i += 128) {
        int f = i >> 7, k = i & 127;
        W2t[k * 128 + f] = w2[i];
        W3t[k * 128 + f] = w3[i];
    }
    float bb2 = b2[t], bb3 = b3[t];
    __syncthreads();
    int row0 = blockIdx.x * 128;
    for (int rg = 0; rg < 128; rg += 4) {
        int r = row0 + rg;
#pragma unroll
        for (int j = 0; j < 4; j++) {
            int rr = r + j;
            as[j * 128 + t] = (rr < N_NODES) ? g_agg[rr * 128 + t] : 0.0f;
        }
        __syncthreads();
        float a0 = 0, a1 = 0, a2 = 0, a3 = 0;
#pragma unroll 8
        for (int k = 0; k < 128; k++) {
            float wv = W2t[k * 128 + t];
            a0 += as[k] * wv;
            a1 += as[128 + k] * wv;
            a2 += as[256 + k] * wv;
            a3 += as[384 + k] * wv;
        }
        tss[0 * 128 + t] = ssp(a0 + bb2);
        tss[1 * 128 + t] = ssp(a1 + bb2);
        tss[2 * 128 + t] = ssp(a2 + bb2);
        tss[3 * 128 + t] = ssp(a3 + bb2);
        __syncthreads();
        float c0 = 0, c1 = 0, c2 = 0, c3 = 0;
#pragma unroll 8
        for (int k = 0; k < 128; k++) {
            float wv = W3t[k * 128 + t];
            c0 += tss[k] * wv;
            c1 += tss[128 + k] * wv;
            c2 += tss[256 + k] * wv;
            c3 += tss[384 + k] * wv;
        }
        if (r + 0 < N_NODES) out[(r + 0) * 128 + t] = c0 + bb3;
        if (r + 1 < N_NODES) out[(r + 1) * 128 + t] = c1 + bb3;
        if (r + 2 < N_NODES) out[(r + 2) * 128 + t] = c2 + bb3;
        if (r + 3 < N_NODES) out[(r + 3) * 128 + t] = c3 + bb3;
        __syncthreads();
    }
}

// ---------------------------------------------------------------- launch
// floats: 6400 + 16384 + 256 + 16*400 + 16*1024 = 45824 floats
#define EDGE_SMEM (45824 * 4)
#define LIN1_SMEM ((16384 + 512) * 4)
#define OUT_SMEM  ((16384 * 2 + 512 + 512) * 4)

extern "C" void kernel_launch(void* const* d_in, const int* in_sizes, int n_in,
                              void* d_out, int out_size) {
    const float* x    = (const float*)d_in[0];
    const int*   ei   = (const int*)d_in[1];
    const float* ew   = (const float*)d_in[2];
    const float* attr = (const float*)d_in[3];
    const int*   col  = (const int*)d_in[4];
    const float* m1w  = (const float*)d_in[5];
    const float* m1b  = (const float*)d_in[6];
    const float* m2w  = (const float*)d_in[7];
    const float* m2b  = (const float*)d_in[8];
    const float* l1w  = (const float*)d_in[9];
    const float* l2w  = (const float*)d_in[10];
    const float* l2b  = (const float*)d_in[11];
    const float* lw   = (const float*)d_in[12];
    const float* lb   = (const float*)d_in[13];
    float* out = (float*)d_out;

    cudaFuncSetAttribute(edge_kernel, cudaFuncAttributeMaxDynamicSharedMemorySize, EDGE_SMEM);
    cudaFuncSetAttribute(lin1_kernel, cudaFuncAttributeMaxDynamicSharedMemorySize, LIN1_SMEM);
    cudaFuncSetAttribute(out_kernel,  cudaFuncAttributeMaxDynamicSharedMemorySize, OUT_SMEM);

    init_kernel<<<2048, 256>>>();
    hist_kernel<<<512, 256>>>(col);
    offset_kernel<<<1, 1>>>();
    scatter_kernel<<<(N_EDGES + SC_BS - 1) / SC_BS, 256>>>(col);
    lin1_kernel<<<(N_NODES + 127) / 128, 128, LIN1_SMEM>>>(x, l1w);
    edge_kernel<<<NCHUNK, 512, EDGE_SMEM>>>(ei, ew, attr, col, m1w, m1b, m2w, m2b);
    out_kernel<<<(N_NODES + 127) / 128, 128, OUT_SMEM>>>(l2w, l2b, lw, lb, out);
}

// round 8
// speedup vs baseline: 1.5839x; 1.1974x over previous
#include <cuda_runtime.h>

#define N_NODES 50000
#define N_EDGES 1000000
#define HIDDEN  128
#define N_GAUSS 50
#define N_FILT  128
#define N_COLORS 4
#define CUTOFF_R 10.0f
#define LOG2F_  0.6931471805599453f
#define PI_F    3.14159265358979323846f

#define CH 1024              // edges per block-chunk (color-aligned)
#define NCHUNK 981           // covers E + max padding
#define PERM_SZ (NCHUNK*CH)  // 1,004,544
#define SC_BS 4096
#define SC_NB 245            // ceil(N_EDGES / SC_BS)
#define L1_NB 391            // ceil(N_NODES / 128)
#define FULLM 0xffffffffu

// ---- scratch (static device globals; zero-initialized at module load) ----
// Invariant: every kernel_launch call leaves g_agg==0 and g_cnt==0 (cleanup
// kernel at the end), matching the initial static state. g_perm uses id+1
// encoding (0 == pad), and the set of written entries is identical every call,
// so it never needs re-initialization.
__device__ float g_h[N_NODES * HIDDEN];     // x @ lin1_w.T
__device__ float g_agg[N_NODES * N_FILT];   // segment-sum accumulator
__device__ int   g_perm[PERM_SZ];           // color-sorted (edge id + 1), 0 = pad
__device__ int   g_cnt[N_COLORS];
__device__ int   g_cur[N_COLORS];

__device__ __forceinline__ float ssp(float v) {
    return fmaxf(v, 0.0f) + __logf(1.0f + __expf(-fabsf(v))) - LOG2F_;
}

// ---- packed f32x2 helpers ----
typedef unsigned long long u64t;

__device__ __forceinline__ u64t dup2(float a) {
    u64t r;
    asm("mov.b64 %0, {%1, %1};" : "=l"(r) : "f"(a));
    return r;
}
__device__ __forceinline__ void fma2(u64t& d, u64t a, u64t b) {
    asm("fma.rn.f32x2 %0, %1, %2, %0;" : "+l"(d) : "l"(a), "l"(b));
}
__device__ __forceinline__ void unpk2(u64t v, float& a, float& b) {
    asm("mov.b64 {%0, %1}, %2;" : "=f"(a), "=f"(b) : "l"(v));
}

// ---------------------------------------------------------------- histogram
__global__ void hist_kernel(const int* __restrict__ colors) {
    __shared__ int sh[N_COLORS];
    if (threadIdx.x < N_COLORS) sh[threadIdx.x] = 0;
    __syncthreads();
    int idx = blockIdx.x * blockDim.x + threadIdx.x;
    int stride = gridDim.x * blockDim.x;
    for (int i = idx; i < N_EDGES; i += stride) atomicAdd(&sh[colors[i]], 1);
    __syncthreads();
    if (threadIdx.x < N_COLORS) atomicAdd(&g_cnt[threadIdx.x], sh[threadIdx.x]);
}

// ---------------------------------------------------------------- offsets (CH-aligned bases)
__global__ void offset_kernel() {
    if (blockIdx.x == 0 && threadIdx.x == 0) {
        int b = 0;
        for (int c = 0; c < N_COLORS; c++) {
            g_cur[c] = b;
            b += (g_cnt[c] + CH - 1) / CH * CH;
        }
    }
}

// ---------------------------------------------------------------- scatter + lin1 (fused launch)
// blocks [0, SC_NB): counting-sort scatter (writes edge id + 1)
// blocks [SC_NB, SC_NB+L1_NB): g_h = x @ lin1_w.T  (tile of 128 rows each)
__global__ void __launch_bounds__(256) scatter_lin1_kernel(
    const int* __restrict__ colors,
    const float* __restrict__ x,
    const float* __restrict__ w)
{
    extern __shared__ float smf[];
    if (blockIdx.x < SC_NB) {
        __shared__ int s_cnt[N_COLORS], s_base[N_COLORS];
        int t = threadIdx.x;
        if (t < N_COLORS) s_cnt[t] = 0;
        __syncthreads();
        int start = blockIdx.x * SC_BS;
        int end = min(start + SC_BS, N_EDGES);
        for (int i = start + t; i < end; i += blockDim.x) atomicAdd(&s_cnt[colors[i]], 1);
        __syncthreads();
        if (t < N_COLORS) { s_base[t] = atomicAdd(&g_cur[t], s_cnt[t]); s_cnt[t] = 0; }
        __syncthreads();
        for (int i = start + t; i < end; i += blockDim.x) {
            int c = colors[i];
            int pos = s_base[c] + atomicAdd(&s_cnt[c], 1);
            g_perm[pos] = i + 1;
        }
    } else {
        int tile = blockIdx.x - SC_NB;
        float* Wt = smf;                 // [k][f] 128*128
        float* xs = Wt + 16384;          // 8*128
        int t = threadIdx.x;
        int th = t & 127, half = t >> 7;
        for (int i = t; i < 16384; i += 256) {
            int f = i >> 7, k = i & 127;
            Wt[k * 128 + f] = w[i];
        }
        __syncthreads();
        int row0 = tile * 128;
        for (int rg = 0; rg < 128; rg += 8) {
            int r = row0 + rg + half * 4;
#pragma unroll
            for (int j = 0; j < 4; j++) {
                int rr = r + j;
                xs[(half * 4 + j) * 128 + th] = (rr < N_NODES) ? x[rr * 128 + th] : 0.0f;
            }
            __syncthreads();
            float a0 = 0, a1 = 0, a2 = 0, a3 = 0;
#pragma unroll 8
            for (int k = 0; k < 128; k++) {
                float wv = Wt[k * 128 + th];
                a0 += xs[(half * 4 + 0) * 128 + k] * wv;
                a1 += xs[(half * 4 + 1) * 128 + k] * wv;
                a2 += xs[(half * 4 + 2) * 128 + k] * wv;
                a3 += xs[(half * 4 + 3) * 128 + k] * wv;
            }
            if (r + 0 < N_NODES) g_h[(r + 0) * 128 + th] = a0;
            if (r + 1 < N_NODES) g_h[(r + 1) * 128 + th] = a1;
            if (r + 2 < N_NODES) g_h[(r + 2) * 128 + th] = a2;
            if (r + 3 < N_NODES) g_h[(r + 3) * 128 + th] = a3;
            __syncthreads();
        }
    }
}

// ---------------------------------------------------------------- fused edge kernel
// One block = one CH-chunk (uniform color). Each warp independently processes
// 64 edges, 8 per iteration, SOFTWARE-PIPELINED:
//   - next tile's metadata + attr prefetched (LDG) at loop top, hidden under MLP1
//   - g_h[src] gather hoisted before MLP2, hidden under ~2000cyc of FMA
__global__ void __launch_bounds__(512, 1) edge_kernel(
    const int* __restrict__ edge_index,
    const float* __restrict__ ew,
    const float* __restrict__ attr,
    const int* __restrict__ colors,
    const float* __restrict__ m1w, const float* __restrict__ m1b,
    const float* __restrict__ m2w, const float* __restrict__ m2b)
{
    extern __shared__ float sm[];
    float* W1t    = sm;                       // 50*128  = 6400 floats
    float* W2t    = W1t + 6400;               // 128*128 = 16384 floats
    float* b1s    = W2t + 16384;              // 128
    float* b2s    = b1s + 128;                // 128
    float* attr_f = b2s + 128;                // 16 warps * 2 bufs * 400 = 12800
    float* hid_f  = attr_f + 12800;           // 16 warps * 1024 = 16384

    int t = threadIdx.x;
    int chunk0 = blockIdx.x * CH;
    int p0c = g_perm[chunk0] - 1;
    if (p0c < 0) return;                      // gap chunk (all pad)
    int c = colors[p0c];

    // load this color's weights (once per block)
    const float* w1 = m1w + c * N_FILT * N_GAUSS;
    for (int i = t; i < N_FILT * N_GAUSS; i += 512) {
        int f = i / N_GAUSS, g = i - f * N_GAUSS;
        W1t[g * 128 + f] = w1[i];
    }
    const float* w2 = m2w + c * N_FILT * N_FILT;
    for (int i = t; i < N_FILT * N_FILT; i += 512) {
        int f = i >> 7, k = i & 127;
        W2t[k * 128 + f] = w2[i];
    }
    if (t < 128) { b1s[t] = m1b[c * 128 + t]; b2s[t] = m2b[c * 128 + t]; }
    __syncthreads();

    int wid = t >> 5;
    int fq  = t & 31;                          // this lane's feature quad
    float* aw0   = attr_f + wid * 800;         // attr buf 0: [g][e] 50*8
    float* aw1   = aw0 + 400;                  // attr buf 1
    float* hid_w = hid_f + wid * 1024;         // [e][k] 8*128

    float4 b1v = *(const float4*)(b1s + fq * 4);
    float4 b2v = *(const float4*)(b2s + fq * 4);

    int ebase = chunk0 + wid * 64;

    // ---- prologue: tile 0 metadata + attr -> aw0 ----
    int csrc = 0, cdst = -1;
    float cC = 0.0f;
    {
        int p = -1;
        if (fq < 8) {
            p = g_perm[ebase + fq] - 1;
            if (p >= 0) {
                csrc = edge_index[p];
                cdst = edge_index[N_EDGES + p];
                cC = 0.5f * (__cosf(ew[p] * (PI_F / CUTOFF_R)) + 1.0f);
            }
        }
        int pe[8];
#pragma unroll
        for (int e = 0; e < 8; e++) pe[e] = __shfl_sync(FULLM, p, e);
#pragma unroll
        for (int i = 0; i < 13; i++) {
            int idx = i * 32 + fq;
            if (idx < 400) {
                int e = idx & 7, g = idx >> 3;
                int q = pe[e];
                float v = (q >= 0) ? __ldg(attr + q * N_GAUSS + g) : 0.0f;
                aw0[idx] = v;
            }
        }
    }
    __syncwarp();

    for (int it = 0; it < 8; it++) {
        float* acur = (it & 1) ? aw1 : aw0;
        float* anxt = (it & 1) ? aw0 : aw1;
        bool hasn = (it < 7);

        // ---- next tile metadata + attr prefetch (LDG -> regs; hidden under MLP1) ----
        int np = -1, nsrc = 0, ndst = -1;
        float nC = 0.0f;
        if (hasn && fq < 8) {
            np = g_perm[ebase + (it + 1) * 8 + fq] - 1;
            if (np >= 0) {
                nsrc = edge_index[np];
                ndst = edge_index[N_EDGES + np];
                nC = 0.5f * (__cosf(ew[np] * (PI_F / CUTOFF_R)) + 1.0f);
            }
        }
        int npe[8];
#pragma unroll
        for (int e = 0; e < 8; e++) npe[e] = __shfl_sync(FULLM, np, e);
        float rpf[13];
#pragma unroll
        for (int i = 0; i < 13; i++) {
            int idx = i * 32 + fq;
            rpf[i] = 0.0f;
            if (hasn && idx < 400) {
                int e = idx & 7, g = idx >> 3;
                int q = npe[e];
                if (q >= 0) rpf[i] = __ldg(attr + q * N_GAUSS + g);
            }
        }

        // ---- MLP1: hidden = ssp(attr @ W1^T + b1) ----
        u64t acc1[8][2];
#pragma unroll
        for (int i = 0; i < 8; i++) { acc1[i][0] = 0ull; acc1[i][1] = 0ull; }
#pragma unroll 5
        for (int g = 0; g < N_GAUSS; g++) {
            ulonglong2 wp = *(const ulonglong2*)(W1t + g * 128 + fq * 4);   // lane-distinct
            float4 a03 = *(const float4*)(acur + g * 8);                    // broadcast
            float4 a47 = *(const float4*)(acur + g * 8 + 4);                // broadcast
            u64t d0 = dup2(a03.x), d1 = dup2(a03.y), d2 = dup2(a03.z), d3 = dup2(a03.w);
            u64t d4 = dup2(a47.x), d5 = dup2(a47.y), d6 = dup2(a47.z), d7 = dup2(a47.w);
            fma2(acc1[0][0], d0, wp.x); fma2(acc1[0][1], d0, wp.y);
            fma2(acc1[1][0], d1, wp.x); fma2(acc1[1][1], d1, wp.y);
            fma2(acc1[2][0], d2, wp.x); fma2(acc1[2][1], d2, wp.y);
            fma2(acc1[3][0], d3, wp.x); fma2(acc1[3][1], d3, wp.y);
            fma2(acc1[4][0], d4, wp.x); fma2(acc1[4][1], d4, wp.y);
            fma2(acc1[5][0], d5, wp.x); fma2(acc1[5][1], d5, wp.y);
            fma2(acc1[6][0], d6, wp.x); fma2(acc1[6][1], d6, wp.y);
            fma2(acc1[7][0], d7, wp.x); fma2(acc1[7][1], d7, wp.y);
        }
        // bias + ssp, store hidden plain: hid_w[e*128 + fq*4..]
#pragma unroll
        for (int ei = 0; ei < 8; ei++) {
            float v0, v1, v2, v3;
            unpk2(acc1[ei][0], v0, v1);
            unpk2(acc1[ei][1], v2, v3);
            float4 hv;
            hv.x = ssp(v0 + b1v.x);
            hv.y = ssp(v1 + b1v.y);
            hv.z = ssp(v2 + b1v.z);
            hv.w = ssp(v3 + b1v.w);
            *(float4*)(hid_w + ei * 128 + fq * 4) = hv;
        }
        // ---- commit prefetched attr to the next buffer ----
#pragma unroll
        for (int i = 0; i < 13; i++) {
            int idx = i * 32 + fq;
            if (hasn && idx < 400) anxt[idx] = rpf[i];
        }
        __syncwarp();

        // ---- g_h[src] gather NOW; latency hides under MLP2 ----
        float4 hvg[8];
#pragma unroll
        for (int ei = 0; ei < 8; ei++) {
            int srce = __shfl_sync(FULLM, csrc, ei);   // pads: src=0, safe addr
            hvg[ei] = *(const float4*)(g_h + srce * 128 + fq * 4);
        }

        // ---- MLP2: W = hidden @ W2^T + b2 ----
        u64t acc2[8][2];
#pragma unroll
        for (int i = 0; i < 8; i++) { acc2[i][0] = 0ull; acc2[i][1] = 0ull; }
#pragma unroll 2
        for (int kc = 0; kc < 32; kc++) {
            ulonglong2 wk0 = *(const ulonglong2*)(W2t + (kc * 4 + 0) * 128 + fq * 4);
            ulonglong2 wk1 = *(const ulonglong2*)(W2t + (kc * 4 + 1) * 128 + fq * 4);
            ulonglong2 wk2 = *(const ulonglong2*)(W2t + (kc * 4 + 2) * 128 + fq * 4);
            ulonglong2 wk3 = *(const ulonglong2*)(W2t + (kc * 4 + 3) * 128 + fq * 4);
#pragma unroll
            for (int ei = 0; ei < 8; ei++) {
                float4 h4 = *(const float4*)(hid_w + ei * 128 + kc * 4);    // broadcast
                u64t d0 = dup2(h4.x), d1 = dup2(h4.y), d2 = dup2(h4.z), d3 = dup2(h4.w);
                fma2(acc2[ei][0], d0, wk0.x); fma2(acc2[ei][1], d0, wk0.y);
                fma2(acc2[ei][0], d1, wk1.x); fma2(acc2[ei][1], d1, wk1.y);
                fma2(acc2[ei][0], d2, wk2.x); fma2(acc2[ei][1], d2, wk2.y);
                fma2(acc2[ei][0], d3, wk3.x); fma2(acc2[ei][1], d3, wk3.y);
            }
        }
        // ---- epilogue: *C, *h[src], scatter-add ----
#pragma unroll
        for (int ei = 0; ei < 8; ei++) {
            int dste = __shfl_sync(FULLM, cdst, ei);   // warp-converged
            float Ce = __shfl_sync(FULLM, cC, ei);
            if (dste >= 0) {                           // warp-uniform branch
                float v0, v1, v2, v3;
                unpk2(acc2[ei][0], v0, v1);
                unpk2(acc2[ei][1], v2, v3);
                float m0 = (v0 + b2v.x) * Ce * hvg[ei].x;
                float m1 = (v1 + b2v.y) * Ce * hvg[ei].y;
                float m2 = (v2 + b2v.z) * Ce * hvg[ei].z;
                float m3 = (v3 + b2v.w) * Ce * hvg[ei].w;
                float* base = g_agg + dste * 128 + fq * 4;
                asm volatile("red.global.add.v4.f32 [%0], {%1, %2, %3, %4};"
                             :: "l"(base), "f"(m0), "f"(m1), "f"(m2), "f"(m3)
                             : "memory");
            }
        }
        // rotate pipeline state
        csrc = nsrc; cdst = ndst; cC = nC;
        __syncwarp();   // protect hid_w / attr bufs for next iteration
    }
}

// ---------------------------------------------------------------- output: ssp(agg@W2^T+b2)@W3^T+b3
__global__ void __launch_bounds__(128) out_kernel(
    const float* __restrict__ w2, const float* __restrict__ b2,
    const float* __restrict__ w3, const float* __restrict__ b3,
    float* __restrict__ out)
{
    extern __shared__ float sm[];
    float* W2t = sm;                // [k][f]
    float* W3t = W2t + 16384;
    float* as  = W3t + 16384;       // 4*128
    float* tss = as + 512;          // 4*128
    int t = threadIdx.x;
    for (int i = t; i < 16384; i += 128) {
        int f = i >> 7, k = i & 127;
        W2t[k * 128 + f] = w2[i];
        W3t[k * 128 + f] = w3[i];
    }
    float bb2 = b2[t], bb3 = b3[t];
    __syncthreads();
    int row0 = blockIdx.x * 128;
    for (int rg = 0; rg < 128; rg += 4) {
        int r = row0 + rg;
#pragma unroll
        for (int j = 0; j < 4; j++) {
            int rr = r + j;
            as[j * 128 + t] = (rr < N_NODES) ? g_agg[rr * 128 + t] : 0.0f;
        }
        __syncthreads();
        float a0 = 0, a1 = 0, a2 = 0, a3 = 0;
#pragma unroll 8
        for (int k = 0; k < 128; k++) {
            float wv = W2t[k * 128 + t];
            a0 += as[k] * wv;
            a1 += as[128 + k] * wv;
            a2 += as[256 + k] * wv;
            a3 += as[384 + k] * wv;
        }
        tss[0 * 128 + t] = ssp(a0 + bb2);
        tss[1 * 128 + t] = ssp(a1 + bb2);
        tss[2 * 128 + t] = ssp(a2 + bb2);
        tss[3 * 128 + t] = ssp(a3 + bb2);
        __syncthreads();
        float c0 = 0, c1 = 0, c2 = 0, c3 = 0;
#pragma unroll 8
        for (int k = 0; k < 128; k++) {
            float wv = W3t[k * 128 + t];
            c0 += tss[k] * wv;
            c1 += tss[128 + k] * wv;
            c2 += tss[256 + k] * wv;
            c3 += tss[384 + k] * wv;
        }
        if (r + 0 < N_NODES) out[(r + 0) * 128 + t] = c0 + bb3;
        if (r + 1 < N_NODES) out[(r + 1) * 128 + t] = c1 + bb3;
        if (r + 2 < N_NODES) out[(r + 2) * 128 + t] = c2 + bb3;
        if (r + 3 < N_NODES) out[(r + 3) * 128 + t] = c3 + bb3;
        __syncthreads();
    }
}

// ---------------------------------------------------------------- cleanup (restore invariant)
__global__ void cleanup_kernel() {
    int idx = blockIdx.x * blockDim.x + threadIdx.x;
    int stride = gridDim.x * blockDim.x;
    for (int i = idx; i < N_NODES * N_FILT; i += stride) g_agg[i] = 0.0f;
    if (idx < N_COLORS) g_cnt[idx] = 0;
}

// ---------------------------------------------------------------- launch
// edge smem floats: 6400+16384+256+12800+16384 = 52224
#define EDGE_SMEM (52224 * 4)
#define SCL_SMEM  ((16384 + 1024) * 4)
#define OUT_SMEM  ((16384 * 2 + 512 + 512) * 4)

extern "C" void kernel_launch(void* const* d_in, const int* in_sizes, int n_in,
                              void* d_out, int out_size) {
    const float* x    = (const float*)d_in[0];
    const int*   ei   = (const int*)d_in[1];
    const float* ew   = (const float*)d_in[2];
    const float* attr = (const float*)d_in[3];
    const int*   col  = (const int*)d_in[4];
    const float* m1w  = (const float*)d_in[5];
    const float* m1b  = (const float*)d_in[6];
    const float* m2w  = (const float*)d_in[7];
    const float* m2b  = (const float*)d_in[8];
    const float* l1w  = (const float*)d_in[9];
    const float* l2w  = (const float*)d_in[10];
    const float* l2b  = (const float*)d_in[11];
    const float* lw   = (const float*)d_in[12];
    const float* lb   = (const float*)d_in[13];
    float* out = (float*)d_out;

    cudaFuncSetAttribute(edge_kernel, cudaFuncAttributeMaxDynamicSharedMemorySize, EDGE_SMEM);
    cudaFuncSetAttribute(scatter_lin1_kernel, cudaFuncAttributeMaxDynamicSharedMemorySize, SCL_SMEM);
    cudaFuncSetAttribute(out_kernel,  cudaFuncAttributeMaxDynamicSharedMemorySize, OUT_SMEM);

    hist_kernel<<<512, 256>>>(col);
    offset_kernel<<<1, 1>>>();
    scatter_lin1_kernel<<<SC_NB + L1_NB, 256, SCL_SMEM>>>(col, x, l1w);
    edge_kernel<<<NCHUNK, 512, EDGE_SMEM>>>(ei, ew, attr, col, m1w, m1b, m2w, m2b);
    out_kernel<<<L1_NB, 128, OUT_SMEM>>>(l2w, l2b, lw, lb, out);
    cleanup_kernel<<<2048, 256>>>();
}